// round 2
// baseline (speedup 1.0000x reference)
#include <cuda_runtime.h>

#define BB      512
#define INF     512
#define OUTF    64
#define KK      16
#define NN      1024   // OUTF * KK
#define OUTCOLS 576    // INF + OUTF

typedef unsigned long long ull;

// Scratch: M = x @ T.reshape(IN, OUT*K), shape (B, 1024), row-major.
__device__ float g_M[BB * NN];

#define FMA2(acc, a, b) \
    asm("fma.rn.f32x2 %0, %1, %2, %0;" : "+l"(acc) : "l"(a), "l"(b))
#define FMA2D(d, a, b, c) \
    asm("fma.rn.f32x2 %0, %1, %2, %3;" : "=l"(d) : "l"(a), "l"(b), "l"(c))
#define ADD2(d, a, b) \
    asm("add.rn.f32x2 %0, %1, %2;" : "=l"(d) : "l"(a), "l"(b))

// ---------------------------------------------------------------------------
// GEMM: M = x(512x512) @ T(512x1024), packed f32x2 FMA.
// Tile 16 rows x 64 cols, k-tile 64, 64 threads, grid (16,32)=512 blocks.
// Each thread: 2 rows x 8 cols (4 packed col-pairs).
// ---------------------------------------------------------------------------
__global__ __launch_bounds__(64) void gemm_kernel(const float* __restrict__ x,
                                                  const float* __restrict__ T) {
    __shared__ __align__(16) float2 As2[64][16];  // [k][row], value duplicated
    __shared__ __align__(16) float  Bs[64][64];   // [k][col]

    const int tid = threadIdx.x;
    const int tx = tid & 7;        // col octet 0..7
    const int ty = tid >> 3;       // row pair 0..7
    const int rowBase = blockIdx.y * 16;
    const int colBase = blockIdx.x * 64;

    ull acc[2][4];
#pragma unroll
    for (int r = 0; r < 2; ++r)
#pragma unroll
        for (int c = 0; c < 4; ++c) acc[r][c] = 0ULL;   // packed (0.f, 0.f)

    for (int k0 = 0; k0 < INF; k0 += 64) {
        // A tile: 16 rows x 64 k = 256 float4; duplicate into float2 pairs
#pragma unroll
        for (int t = tid; t < 256; t += 64) {
            int r  = t >> 4;
            int kg = (t & 15) * 4;
            float4 v = *(const float4*)&x[(rowBase + r) * INF + k0 + kg];
            As2[kg + 0][r] = make_float2(v.x, v.x);
            As2[kg + 1][r] = make_float2(v.y, v.y);
            As2[kg + 2][r] = make_float2(v.z, v.z);
            As2[kg + 3][r] = make_float2(v.w, v.w);
        }
        // B tile: 64 k x 64 cols = 1024 float4, coalesced
#pragma unroll
        for (int t = tid; t < 1024; t += 64) {
            int r  = t >> 4;
            int cg = (t & 15) * 4;
            *(float4*)&Bs[r][cg] = *(const float4*)&T[(k0 + r) * NN + colBase + cg];
        }
        __syncthreads();

#pragma unroll 16
        for (int kk = 0; kk < 64; ++kk) {
            ulonglong2 av = *(const ulonglong2*)&As2[kk][ty * 2];     // 2 rows, dup pairs
            ulonglong2 b0 = *(const ulonglong2*)&Bs[kk][tx * 8];      // cols 0..3
            ulonglong2 b1 = *(const ulonglong2*)&Bs[kk][tx * 8 + 4];  // cols 4..7
            FMA2(acc[0][0], av.x, b0.x);
            FMA2(acc[0][1], av.x, b0.y);
            FMA2(acc[0][2], av.x, b1.x);
            FMA2(acc[0][3], av.x, b1.y);
            FMA2(acc[1][0], av.y, b0.x);
            FMA2(acc[1][1], av.y, b0.y);
            FMA2(acc[1][2], av.y, b1.x);
            FMA2(acc[1][3], av.y, b1.y);
        }
        __syncthreads();
    }

#pragma unroll
    for (int r = 0; r < 2; ++r) {
        int row = rowBase + ty * 2 + r;
        ulonglong2 v0, v1;
        v0.x = acc[r][0]; v0.y = acc[r][1];
        v1.x = acc[r][2]; v1.y = acc[r][3];
        *(ulonglong2*)&g_M[row * NN + colBase + tx * 8]     = v0;
        *(ulonglong2*)&g_M[row * NN + colBase + tx * 8 + 4] = v1;
    }
}

// ---------------------------------------------------------------------------
// Pairwise: block (o, ic): smem holds M[:, o, :] (512x16 = 32KB).
// Thread i: sum_j exp(-sum_k |M[i,o,k]-M[j,o,k]|) - 1, packed f32x2 math.
// ---------------------------------------------------------------------------
__global__ __launch_bounds__(64) void pairwise_kernel(float* __restrict__ out) {
    __shared__ __align__(16) float sM[BB * KK];   // 32 KB

    const int o   = blockIdx.x;
    const int ic  = blockIdx.y;
    const int tid = threadIdx.x;

    // Gather column-o slice: g_M[j*1024 + o*16 + k] -> sM[j*16 + k]
#pragma unroll
    for (int t = tid; t < BB * 4; t += 64) {
        int j = t >> 2;
        int q = t & 3;
        *(float4*)&sM[j * KK + q * 4] = *(const float4*)&g_M[j * NN + o * KK + q * 4];
    }
    __syncthreads();

    const int i = ic * 64 + tid;
    ull mi[8];
    {
        const ulonglong2* mrow = (const ulonglong2*)&sM[i * KK];
        ulonglong2 m0 = mrow[0], m1 = mrow[1], m2 = mrow[2], m3 = mrow[3];
        mi[0] = m0.x; mi[1] = m0.y; mi[2] = m1.x; mi[3] = m1.y;
        mi[4] = m2.x; mi[5] = m2.y; mi[6] = m3.x; mi[7] = m3.y;
    }

    const ull NEG1  = 0xBF800000BF800000ULL;   // (-1.f, -1.f)
    const ull AMASK = 0x7FFFFFFF7FFFFFFFULL;

    float acc = 0.f;
#pragma unroll 2
    for (int j = 0; j < BB; ++j) {
        const ulonglong2* p = (const ulonglong2*)&sM[j * KK];
        ulonglong2 p0 = p[0], p1 = p[1], p2 = p[2], p3 = p[3];

        ull d0, d1, d2, d3, d4, d5, d6, d7;
        FMA2D(d0, p0.x, NEG1, mi[0]);   // mi - b, 2 lanes
        FMA2D(d1, p0.y, NEG1, mi[1]);
        FMA2D(d2, p1.x, NEG1, mi[2]);
        FMA2D(d3, p1.y, NEG1, mi[3]);
        FMA2D(d4, p2.x, NEG1, mi[4]);
        FMA2D(d5, p2.y, NEG1, mi[5]);
        FMA2D(d6, p3.x, NEG1, mi[6]);
        FMA2D(d7, p3.y, NEG1, mi[7]);

        d0 &= AMASK; d1 &= AMASK; d2 &= AMASK; d3 &= AMASK;   // |.| on ALU pipe
        d4 &= AMASK; d5 &= AMASK; d6 &= AMASK; d7 &= AMASK;

        ull s0, s1, s2, s3, t0, t1, tt;
        ADD2(s0, d0, d1);
        ADD2(s1, d2, d3);
        ADD2(s2, d4, d5);
        ADD2(s3, d6, d7);
        ADD2(t0, s0, s1);
        ADD2(t1, s2, s3);
        ADD2(tt, t0, t1);

        float lo = __uint_as_float((unsigned int)tt);
        float hi = __uint_as_float((unsigned int)(tt >> 32));
        float norm = lo + hi;

        acc += __expf(-norm);          // j==i contributes exactly 1.0
    }

    out[i * OUTCOLS + INF + o] = acc - 1.0f;
}

// ---------------------------------------------------------------------------
// Copy x into the first 512 columns of each output row.
// ---------------------------------------------------------------------------
__global__ __launch_bounds__(256) void copy_x_kernel(const float* __restrict__ x,
                                                     float* __restrict__ out) {
    int idx = blockIdx.x * blockDim.x + threadIdx.x;  // over 512*128 float4
    int i = idx >> 7;        // row
    int c = idx & 127;       // float4 index within row
    float4 v = *(const float4*)&x[i * INF + c * 4];
    *(float4*)&out[i * OUTCOLS + c * 4] = v;
}

extern "C" void kernel_launch(void* const* d_in, const int* in_sizes, int n_in,
                              void* d_out, int out_size) {
    const float* x = (const float*)d_in[0];
    const float* T = (const float*)d_in[1];
    float* out = (float*)d_out;

    gemm_kernel<<<dim3(NN / 64, BB / 16), 64>>>(x, T);
    pairwise_kernel<<<dim3(OUTF, 8), 64>>>(out);
    copy_x_kernel<<<(BB * (INF / 4)) / 256, 256>>>(x, out);
}

// round 3
// speedup vs baseline: 1.8756x; 1.8756x over previous
#include <cuda_runtime.h>

#define BB      512
#define INF     512
#define OUTF    64
#define KK      16
#define NN      1024   // OUTF * KK
#define OUTCOLS 576    // INF + OUTF

typedef unsigned long long ull;

// Scratch: M = x @ T.reshape(IN, OUT*K), shape (B, 1024), row-major.
__device__ float g_M[BB * NN];

#define FMA2D(d, a, b, c) \
    asm("fma.rn.f32x2 %0, %1, %2, %3;" : "=l"(d) : "l"(a), "l"(b), "l"(c))
#define ADD2(d, a, b) \
    asm("add.rn.f32x2 %0, %1, %2;" : "=l"(d) : "l"(a), "l"(b))

__device__ __forceinline__ unsigned f2tf32(float f) {
    unsigned u;
    asm("cvt.rna.tf32.f32 %0, %1;" : "=r"(u) : "f"(f));
    return u;
}

__device__ __forceinline__ void mma_tf32(float* c, const unsigned* a, const unsigned* b) {
    asm("mma.sync.aligned.m16n8k8.row.col.f32.tf32.tf32.f32 "
        "{%0,%1,%2,%3}, {%4,%5,%6,%7}, {%8,%9}, {%0,%1,%2,%3};"
        : "+f"(c[0]), "+f"(c[1]), "+f"(c[2]), "+f"(c[3])
        : "r"(a[0]), "r"(a[1]), "r"(a[2]), "r"(a[3]), "r"(b[0]), "r"(b[1]));
}

// ---------------------------------------------------------------------------
// GEMM via tf32 tensor cores: M = x(512x512) @ T(512x1024).
// Block: 128 threads (4 warps, 2x2), tile 64x64, k-tile 32.
// Warp computes 32x32 = 2 m-tiles x 4 n-tiles of m16n8k8.
// ---------------------------------------------------------------------------
__global__ __launch_bounds__(128) void gemm_tc(const float* __restrict__ x,
                                               const float* __restrict__ T) {
    __shared__ float As[64][36];   // [row][k], pad 36 -> conflict-free gathers
    __shared__ float Bs[32][68];   // [k][n],  pad 68

    const int tid  = threadIdx.x;
    const int warp = tid >> 5;
    const int lane = tid & 31;
    const int wm   = warp & 1;     // warp row (0..1)
    const int wn   = warp >> 1;    // warp col (0..1)
    const int tg   = lane >> 2;    // group id 0..7
    const int tig  = lane & 3;     // thread-in-group 0..3

    const int rowBase = blockIdx.y * 64;
    const int colBase = blockIdx.x * 64;

    float acc[2][4][4];
#pragma unroll
    for (int mt = 0; mt < 2; ++mt)
#pragma unroll
        for (int nt = 0; nt < 4; ++nt)
#pragma unroll
            for (int q = 0; q < 4; ++q) acc[mt][nt][q] = 0.f;

    for (int k0 = 0; k0 < INF; k0 += 32) {
        // A tile: 64 rows x 32 k = 512 float4, 4 per thread
#pragma unroll
        for (int t = tid; t < 512; t += 128) {
            int r  = t >> 3;
            int kq = (t & 7) * 4;
            *(float4*)&As[r][kq] = *(const float4*)&x[(rowBase + r) * INF + k0 + kq];
        }
        // B tile: 32 k x 64 n = 512 float4, 4 per thread (coalesced)
#pragma unroll
        for (int t = tid; t < 512; t += 128) {
            int kk = t >> 4;
            int nq = (t & 15) * 4;
            *(float4*)&Bs[kk][nq] = *(const float4*)&T[(k0 + kk) * NN + colBase + nq];
        }
        __syncthreads();

#pragma unroll
        for (int ks = 0; ks < 32; ks += 8) {
            unsigned a[2][4], b[4][2];
#pragma unroll
            for (int mt = 0; mt < 2; ++mt) {
                int rowA = wm * 32 + mt * 16 + tg;
                a[mt][0] = f2tf32(As[rowA][ks + tig]);
                a[mt][1] = f2tf32(As[rowA + 8][ks + tig]);
                a[mt][2] = f2tf32(As[rowA][ks + tig + 4]);
                a[mt][3] = f2tf32(As[rowA + 8][ks + tig + 4]);
            }
#pragma unroll
            for (int nt = 0; nt < 4; ++nt) {
                int colB = wn * 32 + nt * 8 + tg;
                b[nt][0] = f2tf32(Bs[ks + tig][colB]);
                b[nt][1] = f2tf32(Bs[ks + tig + 4][colB]);
            }
#pragma unroll
            for (int mt = 0; mt < 2; ++mt)
#pragma unroll
                for (int nt = 0; nt < 4; ++nt)
                    mma_tf32(acc[mt][nt], a[mt], b[nt]);
        }
        __syncthreads();
    }

    // Epilogue: c0,c1 at (row, tig*2..+1); c2,c3 at (row+8, same cols)
#pragma unroll
    for (int mt = 0; mt < 2; ++mt) {
#pragma unroll
        for (int nt = 0; nt < 4; ++nt) {
            int row0 = rowBase + wm * 32 + mt * 16 + tg;
            int col0 = colBase + wn * 32 + nt * 8 + tig * 2;
            *(float2*)&g_M[row0 * NN + col0]       = make_float2(acc[mt][nt][0], acc[mt][nt][1]);
            *(float2*)&g_M[(row0 + 8) * NN + col0] = make_float2(acc[mt][nt][2], acc[mt][nt][3]);
        }
    }
}

// ---------------------------------------------------------------------------
// Pairwise + folded x-copy. Grid (65, 4), 256 threads.
//   o < 64 : block (o, ic) computes o_b[i, o] for i in [ic*128, ic*128+128).
//            Two threads per i, each sweeps 256 j's; smem reduce at the end.
//   o == 64: block ic copies x rows [ic*128, +128) into out.
// ---------------------------------------------------------------------------
__global__ __launch_bounds__(256) void pairwise_kernel(const float* __restrict__ x,
                                                       float* __restrict__ out) {
    __shared__ __align__(16) float sM[BB * KK];   // 32 KB
    __shared__ float part[256];

    const int o   = blockIdx.x;
    const int ic  = blockIdx.y;
    const int tid = threadIdx.x;

    if (o == OUTF) {
        // copy 128 rows of x into out[:, 0:512]
        int base = ic * 128;
#pragma unroll
        for (int t = tid; t < 128 * (INF / 4); t += 256) {
            int r = t >> 7;          // 0..127
            int c = t & 127;         // float4 idx
            float4 v = *(const float4*)&x[(base + r) * INF + c * 4];
            *(float4*)&out[(base + r) * OUTCOLS + c * 4] = v;
        }
        return;
    }

    // Gather column-o slice: g_M[j*1024 + o*16 + k] -> sM[j*16 + k]
#pragma unroll
    for (int t = tid; t < BB * 4; t += 256) {
        int j = t >> 2;
        int q = t & 3;
        *(float4*)&sM[j * KK + q * 4] = *(const float4*)&g_M[j * NN + o * KK + q * 4];
    }
    __syncthreads();

    const int i     = ic * 128 + (tid & 127);
    const int jbase = (tid >> 7) * 256;   // 0 or 256

    ull mi[8];
    {
        const ulonglong2* mrow = (const ulonglong2*)&sM[i * KK];
        ulonglong2 m0 = mrow[0], m1 = mrow[1], m2 = mrow[2], m3 = mrow[3];
        mi[0] = m0.x; mi[1] = m0.y; mi[2] = m1.x; mi[3] = m1.y;
        mi[4] = m2.x; mi[5] = m2.y; mi[6] = m3.x; mi[7] = m3.y;
    }

    const ull NEG1  = 0xBF800000BF800000ULL;   // (-1.f, -1.f)
    const ull AMASK = 0x7FFFFFFF7FFFFFFFULL;

    float acc = 0.f;
#pragma unroll 2
    for (int jj = 0; jj < 256; ++jj) {
        const int j = jbase + jj;
        const ulonglong2* p = (const ulonglong2*)&sM[j * KK];
        ulonglong2 p0 = p[0], p1 = p[1], p2 = p[2], p3 = p[3];

        ull d0, d1, d2, d3, d4, d5, d6, d7;
        FMA2D(d0, p0.x, NEG1, mi[0]);   // mi - mj, 2 lanes
        FMA2D(d1, p0.y, NEG1, mi[1]);
        FMA2D(d2, p1.x, NEG1, mi[2]);
        FMA2D(d3, p1.y, NEG1, mi[3]);
        FMA2D(d4, p2.x, NEG1, mi[4]);
        FMA2D(d5, p2.y, NEG1, mi[5]);
        FMA2D(d6, p3.x, NEG1, mi[6]);
        FMA2D(d7, p3.y, NEG1, mi[7]);

        d0 &= AMASK; d1 &= AMASK; d2 &= AMASK; d3 &= AMASK;   // |.| on ALU pipe
        d4 &= AMASK; d5 &= AMASK; d6 &= AMASK; d7 &= AMASK;

        ull s0, s1, s2, s3, t0, t1, tt;
        ADD2(s0, d0, d1);
        ADD2(s1, d2, d3);
        ADD2(s2, d4, d5);
        ADD2(s3, d6, d7);
        ADD2(t0, s0, s1);
        ADD2(t1, s2, s3);
        ADD2(tt, t0, t1);

        float lo = __uint_as_float((unsigned int)tt);
        float hi = __uint_as_float((unsigned int)(tt >> 32));
        float norm = lo + hi;

        acc += __expf(-norm);          // j==i contributes exactly 1.0
    }

    part[tid] = acc;
    __syncthreads();
    if (tid < 128) {
        out[i * OUTCOLS + INF + o] = part[tid] + part[tid + 128] - 1.0f;
    }
}

extern "C" void kernel_launch(void* const* d_in, const int* in_sizes, int n_in,
                              void* d_out, int out_size) {
    const float* x = (const float*)d_in[0];
    const float* T = (const float*)d_in[1];
    float* out = (float*)d_out;

    gemm_tc<<<dim3(NN / 64, BB / 64), 128>>>(x, T);
    pairwise_kernel<<<dim3(OUTF + 1, 4), 256>>>(x, out);
}